// round 2
// baseline (speedup 1.0000x reference)
#include <cuda_runtime.h>
#include <cstdint>

#define NB 128
#define NT 256
#define BB 16
#define TT 1024
#define DD 1024
#define SS 512
#define MM 16

// ---------------- persistent state (device globals; no allocation) ----------
__device__ float g_h[BB * DD];
__device__ float g_c[BB * DD];
__device__ float g_ctx[BB * DD];
__device__ float g_gpart[4][BB][4 * DD];   // k-split partial gates, 1 MB
__device__ float g_watt[BB][SS];
__device__ unsigned g_count;               // zero-initialized
__device__ volatile unsigned g_gen;

__device__ __forceinline__ float sigf(float x) {
    return __fdividef(1.0f, 1.0f + __expf(-x));
}

// Software grid barrier. Safe: grid = 128 blocks <= 148+ SMs => single wave,
// all blocks co-resident.
__device__ __forceinline__ void grid_barrier() {
    __syncthreads();
    if (threadIdx.x == 0) {
        unsigned gen = g_gen;
        __threadfence();
        unsigned arrived = atomicAdd(&g_count, 1u);
        if (arrived == NB - 1) {
            g_count = 0u;
            __threadfence();
            g_gen = gen + 1u;
        } else {
            while (g_gen == gen) { __nanosleep(64); }
            __threadfence();
        }
    }
    __syncthreads();
}

extern __shared__ float smem[];  // 12288 floats = 48 KB (dynamic only; no
                                 // static __shared__ anywhere -> launch fits
                                 // the 48KB default limit without opt-in)

__global__ __launch_bounds__(NT, 1) void tts_kernel(
    const float* __restrict__ x_in,    // [B,T,D]
    const float* __restrict__ memv,    // [B,S,D]
    const int*   __restrict__ lens,    // [B]
    const float* __restrict__ W_ih,    // [4096,2048]
    const float* __restrict__ W_hh,    // [4096,1024]
    const float* __restrict__ b_ih,    // [4096]
    const float* __restrict__ b_hh,    // [4096]
    const float* __restrict__ Wg_w,    // [48,1024]
    const float* __restrict__ Wg_b,    // [48]
    float* __restrict__ out)
{
    const int bid = blockIdx.x;
    const int tid = threadIdx.x;

    // Small per-phase scratch carved from dynamic smem (phase-disjoint with
    // the x-staging and ctx-reduction uses of the same bytes; every phase
    // boundary crosses a grid_barrier()/__syncthreads()).
    float* sh_phi   = smem;        // 48 floats
    float* sh_ksi   = smem + 48;   // 16
    float* sh_binv  = smem + 64;   // 16
    float* sh_alpha = smem + 80;   // 16

    float* out_ctx   = out;                                  // [B,1,D]
    float* out_align = out + BB * DD;                        // [B,T,S]
    float* out_term  = out + BB * DD + (size_t)BB * TT * SS; // [B,1]

    // ------- init state (every launch; deterministic) -------
    for (int i = bid * NT + tid; i < BB * DD; i += NB * NT) {
        g_h[i] = 0.0f; g_c[i] = 0.0f; g_ctx[i] = 0.0f;
    }
    grid_barrier();

    // gates GEMM mapping: 32 j-tiles x 4 k-splits
    const int jt = bid >> 2;            // 0..31 -> 128 j's each
    const int kb = bid & 3;             // 0..3  -> 768 k's each
    const int jj = tid >> 3;            // 0..31 (j-group of 4 within tile)
    const int ks = tid & 7;             // 0..7  (k slice within group)
    const int j0 = jt * 128 + jj * 4;
    const int kbase = kb * 768;

    for (int t = 0; t < TT; ++t) {
        // ===================== stage x slice into smem =====================
        // layout: xs[cb][kl] = float4 of x for batches 4cb..4cb+3 at k=kbase+kl
        for (int b = 0; b < BB; ++b) {
            const int cb = b >> 2, bl = b & 3;
            for (int kl = tid; kl < 768; kl += NT) {
                const int k = kbase + kl;
                float v;
                if (k < DD)            v = x_in[((size_t)b * TT + t) * DD + k];
                else if (k < 2 * DD)   v = g_ctx[b * DD + (k - DD)];
                else                   v = g_h[b * DD + (k - 2 * DD)];
                smem[cb * 3072 + kl * 4 + bl] = v;
            }
        }
        __syncthreads();

        // ===================== gates GEMM (packed f32x2) ===================
        {
            unsigned long long acc[4][8];
            #pragma unroll
            for (int a = 0; a < 4; ++a)
                #pragma unroll
                for (int p = 0; p < 8; ++p) acc[a][p] = 0ull;

            const float* rowA0 = W_ih + (size_t)j0 * 2048;
            const float* rowB0 = W_hh + (size_t)j0 * 1024;

            for (int it = 0; it < 96; ++it) {
                const int kl = it * 8 + ks;
                const int k  = kbase + kl;
                // x: 8 packed pairs (b=0..15), conflict-free 128B LDS rows
                unsigned long long xv[8];
                #pragma unroll
                for (int cb = 0; cb < 4; ++cb) {
                    const double2 d2 = *reinterpret_cast<const double2*>(
                        &smem[cb * 3072 + kl * 4]);
                    xv[cb * 2]     = __double_as_longlong(d2.x);
                    xv[cb * 2 + 1] = __double_as_longlong(d2.y);
                }
                #pragma unroll
                for (int a = 0; a < 4; ++a) {
                    const float wv = (k < 2048)
                        ? rowA0[(size_t)a * 2048 + k]
                        : rowB0[(size_t)a * 1024 + (k - 2048)];
                    unsigned long long w2;
                    asm("mov.b64 %0, {%1, %1};" : "=l"(w2) : "r"(__float_as_uint(wv)));
                    #pragma unroll
                    for (int p = 0; p < 8; ++p)
                        asm("fma.rn.f32x2 %0, %1, %2, %0;"
                            : "+l"(acc[a][p]) : "l"(w2), "l"(xv[p]));
                }
            }
            // reduce across the 8 k-slice lanes (butterfly within width-8 group)
            #pragma unroll
            for (int off = 4; off >= 1; off >>= 1) {
                #pragma unroll
                for (int a = 0; a < 4; ++a)
                    #pragma unroll
                    for (int p = 0; p < 8; ++p) {
                        unsigned lo = (unsigned)acc[a][p];
                        unsigned hi = (unsigned)(acc[a][p] >> 32);
                        lo = __shfl_xor_sync(0xFFFFFFFFu, lo, off, 8);
                        hi = __shfl_xor_sync(0xFFFFFFFFu, hi, off, 8);
                        unsigned long long o = ((unsigned long long)hi << 32) | lo;
                        asm("add.rn.f32x2 %0, %0, %1;" : "+l"(acc[a][p]) : "l"(o));
                    }
            }
            // lane ks owns batch pair (2ks, 2ks+1); static-index selection
            #pragma unroll
            for (int p = 0; p < 8; ++p) {
                if (p == ks) {
                    const int b0 = p * 2;
                    #pragma unroll
                    for (int a = 0; a < 4; ++a) {
                        const unsigned long long v = acc[a][p];
                        g_gpart[kb][b0][j0 + a]     = __uint_as_float((unsigned)v);
                        g_gpart[kb][b0 + 1][j0 + a] = __uint_as_float((unsigned)(v >> 32));
                    }
                }
            }
        }
        grid_barrier();  // B1: gates done (staging smem now dead)

        // ============ LSTM + phi + GMM attention (blocks 0..15) ============
        if (bid < BB) {
            const int b = bid;
            for (int dd = tid; dd < DD; dd += NT) {
                float gi = b_ih[dd]          + b_hh[dd];
                float gf = b_ih[DD + dd]     + b_hh[DD + dd];
                float gg = b_ih[2 * DD + dd] + b_hh[2 * DD + dd];
                float go = b_ih[3 * DD + dd] + b_hh[3 * DD + dd];
                #pragma unroll
                for (int q = 0; q < 4; ++q) {
                    gi += g_gpart[q][b][dd];
                    gf += g_gpart[q][b][DD + dd];
                    gg += g_gpart[q][b][2 * DD + dd];
                    go += g_gpart[q][b][3 * DD + dd];
                }
                const float c = sigf(gf) * g_c[b * DD + dd] + sigf(gi) * tanhf(gg);
                const float h = sigf(go) * tanhf(c);
                g_c[b * DD + dd] = c;
                g_h[b * DD + dd] = h;
            }
            __syncthreads();

            // phi = h @ Wg_w^T + Wg_b  (48 dots of 1024; warp w -> 6 rows)
            {
                const int w = tid >> 5, lane = tid & 31;
                float hreg[32];
                #pragma unroll
                for (int i = 0; i < 32; ++i) hreg[i] = g_h[b * DD + i * 32 + lane];
                for (int mi = 0; mi < 6; ++mi) {
                    const int mm = w * 6 + mi;
                    const float* wr = Wg_w + (size_t)mm * DD;
                    float acc = 0.0f;
                    #pragma unroll
                    for (int i = 0; i < 32; ++i) acc += wr[i * 32 + lane] * hreg[i];
                    #pragma unroll
                    for (int off = 16; off; off >>= 1)
                        acc += __shfl_xor_sync(0xFFFFFFFFu, acc, off);
                    if (lane == 0) sh_phi[mm] = acc + Wg_b[mm];
                }
            }
            __syncthreads();

            if (tid < 32) {
                const int m = tid & 15;
                const float pk = sh_phi[m];
                const float pb = sh_phi[MM + m];
                const float pa = sh_phi[2 * MM + m];
                float mx = pa;
                #pragma unroll
                for (int off = 1; off < 16; off <<= 1)
                    mx = fmaxf(mx, __shfl_xor_sync(0xFFFFFFFFu, mx, off, 16));
                const float e = __expf(pa - mx);
                float sum = e;
                #pragma unroll
                for (int off = 1; off < 16; off <<= 1)
                    sum += __shfl_xor_sync(0xFFFFFFFFu, sum, off, 16);
                if (tid < 16) {
                    sh_alpha[m] = e / sum;
                    sh_ksi[m]   = __expf(pk);
                    sh_binv[m]  = __expf(-pb);
                }
            }
            __syncthreads();

            // attention weights w[b,s] + termination tap
            const int lb = lens[b];
            for (int s = tid; s < SS; s += NT) {
                const float fs = (float)s;
                float aw = 0.0f, ar = 0.0f;
                #pragma unroll
                for (int m = 0; m < MM; ++m) {
                    const float binv = sh_binv[m];
                    const float z  = (fs - sh_ksi[m]) * binv;
                    const float hb = 0.5f * binv;
                    const float fr = sigf(z + hb);
                    const float fl = sigf(z - hb);
                    const float al = sh_alpha[m];
                    aw += al * (fr - fl);
                    ar += al * fr;
                }
                g_watt[b][s] = aw;
                out_align[((size_t)b * TT + t) * SS + s] = aw;
                if (t == TT - 1 && s == lb - 1) out_term[b] = 1.0f - ar;
            }
        }
        grid_barrier();  // B2: h, w ready (sh arrays now dead)

        // ===================== ctx = w @ memory ============================
        {
            const int b  = bid >> 3;
            const int d0 = (bid & 7) * 128;
            const int w  = tid >> 5, lane = tid & 31;
            const float* mb = memv + (size_t)b * SS * DD + d0 + lane * 4;
            float4 acc = make_float4(0.f, 0.f, 0.f, 0.f);
            const int sbase = w * 64;
            for (int si = 0; si < 64; ++si) {
                const int s = sbase + si;
                const float wv = g_watt[b][s];
                const float4 mv = *reinterpret_cast<const float4*>(mb + (size_t)s * DD);
                acc.x += wv * mv.x; acc.y += wv * mv.y;
                acc.z += wv * mv.z; acc.w += wv * mv.w;
            }
            float4* red = reinterpret_cast<float4*>(smem);
            red[w * 32 + lane] = acc;
            __syncthreads();
            if (tid < 32) {
                float4 r = red[tid];
                #pragma unroll
                for (int q = 1; q < 8; ++q) {
                    const float4 v = red[q * 32 + tid];
                    r.x += v.x; r.y += v.y; r.z += v.z; r.w += v.w;
                }
                const int di = d0 + tid * 4;
                *reinterpret_cast<float4*>(&g_ctx[b * DD + di]) = r;
                if (t == TT - 1)
                    *reinterpret_cast<float4*>(&out_ctx[b * DD + di]) = r;
            }
        }
        grid_barrier();  // B3: ctx ready for next step's gates
    }
}

extern "C" void kernel_launch(void* const* d_in, const int* in_sizes, int n_in,
                              void* d_out, int out_size) {
    (void)in_sizes; (void)n_in; (void)out_size;
    const float* x_in  = (const float*)d_in[0];
    const float* memv  = (const float*)d_in[1];
    const int*   lens  = (const int*)  d_in[2];
    const float* W_ih  = (const float*)d_in[3];
    const float* W_hh  = (const float*)d_in[4];
    const float* b_ih  = (const float*)d_in[5];
    const float* b_hh  = (const float*)d_in[6];
    const float* Wg_w  = (const float*)d_in[7];
    const float* Wg_b  = (const float*)d_in[8];
    tts_kernel<<<NB, NT, 49152>>>(x_in, memv, lens, W_ih, W_hh,
                                  b_ih, b_hh, Wg_w, Wg_b, (float*)d_out);
}

// round 3
// speedup vs baseline: 1.0450x; 1.0450x over previous
#include <cuda_runtime.h>
#include <cstdint>

#define NB 128
#define NT 256
#define BB 16
#define TT 1024
#define DD 1024
#define SS 512
#define MM 16

// ---------------- persistent state (device globals; no allocation) ----------
__device__ float g_h[BB * DD];
__device__ float g_c[BB * DD];
__device__ float g_ctx[BB * DD];
__device__ float g_gpart[4][BB][4 * DD];   // k-split partial gates, 1 MB
__device__ float g_watt[BB][SS];
__device__ unsigned g_count;               // zero-initialized
__device__ volatile unsigned g_gen;

__device__ __forceinline__ float sigf(float x) {
    return __fdividef(1.0f, 1.0f + __expf(-x));
}

// Software grid barrier. Grid = 128 blocks <= 148 SMs => single wave,
// all blocks co-resident.
__device__ __forceinline__ void grid_barrier() {
    __syncthreads();
    if (threadIdx.x == 0) {
        unsigned gen = g_gen;
        __threadfence();
        unsigned arrived = atomicAdd(&g_count, 1u);
        if (arrived == NB - 1) {
            g_count = 0u;
            __threadfence();
            g_gen = gen + 1u;
        } else {
            while (g_gen == gen) { __nanosleep(32); }
            __threadfence();
        }
    }
    __syncthreads();
}

extern __shared__ float smem[];  // 12288 floats = 48 KB dynamic only

__global__ __launch_bounds__(NT, 1) void tts_kernel(
    const float* __restrict__ x_in,    // [B,T,D]
    const float* __restrict__ memv,    // [B,S,D]
    const int*   __restrict__ lens,    // [B]
    const float* __restrict__ W_ih,    // [4096,2048]
    const float* __restrict__ W_hh,    // [4096,1024]
    const float* __restrict__ b_ih,    // [4096]
    const float* __restrict__ b_hh,    // [4096]
    const float* __restrict__ Wg_w,    // [48,1024]
    const float* __restrict__ Wg_b,    // [48]
    float* __restrict__ out)
{
    const int bid = blockIdx.x;
    const int tid = threadIdx.x;

    // phase-disjoint small scratch carved from dynamic smem
    float* sh_phi   = smem;        // 48 floats
    float* sh_ksi   = smem + 48;   // 16
    float* sh_binv  = smem + 64;   // 16
    float* sh_alpha = smem + 80;   // 16

    float* out_ctx   = out;                                  // [B,1,D]
    float* out_align = out + BB * DD;                        // [B,T,S]
    float* out_term  = out + BB * DD + (size_t)BB * TT * SS; // [B,1]

    // ------- init state -------
    for (int i = bid * NT + tid; i < BB * DD; i += NB * NT) {
        g_h[i] = 0.0f; g_c[i] = 0.0f; g_ctx[i] = 0.0f;
    }
    grid_barrier();

    // gates GEMM mapping: 32 j-tiles x 4 k-splits
    const int jt = bid >> 2;            // 0..31 -> 128 j's each
    const int kb = bid & 3;             // 0..3  -> 768 k's each
    const int kbase = kb * 768;

    // within block: 16 j-groups (8 rows each) x [2 batch-groups x 8 k-slices]
    const int jg    = tid >> 4;         // 0..15
    const int lane4 = tid & 15;
    const int bg    = lane4 & 1;        // batch group: batches bg*8 .. bg*8+7
    const int ksl   = lane4 >> 1;       // 0..7 k-slice (24 quads each)
    const int j0t   = jt * 128 + jg * 8;

    const float* wih = W_ih + (size_t)j0t * 2048;
    const float* whh = W_hh + (size_t)j0t * 1024;

    for (int t = 0; t < TT; ++t) {
        // ===================== stage x slice into smem =====================
        // xs[cb][kl] = float4 of x for batches 4cb..4cb+3 at k = kbase+kl
        #pragma unroll 2
        for (int b = 0; b < BB; ++b) {
            const int cb = b >> 2, bl = b & 3;
            #pragma unroll
            for (int r = 0; r < 3; ++r) {
                const int kl = r * NT + tid;
                const int k = kbase + kl;
                float v;
                if (k < DD)            v = x_in[((size_t)b * TT + t) * DD + k];
                else if (k < 2 * DD)   v = g_ctx[b * DD + (k - DD)];
                else                   v = g_h[b * DD + (k - 2 * DD)];
                smem[cb * 3072 + kl * 4 + bl] = v;
            }
        }
        __syncthreads();

        // ======= gates GEMM: float4 weights, prefetch, packed f32x2 =======
        {
            unsigned long long acc[8][4];
            #pragma unroll
            for (int a = 0; a < 8; ++a)
                #pragma unroll
                for (int p = 0; p < 4; ++p) acc[a][p] = 0ull;

            float4 wc[8], wn[8];

            auto ldw = [&](float4* dst, int i) {
                const int off = (i * 8 + ksl) * 4;   // 0..767
                const int k = kbase + off;
                if (k < 2048) {
                    const float* p = wih + k;
                    #pragma unroll
                    for (int a = 0; a < 8; ++a)
                        dst[a] = *reinterpret_cast<const float4*>(p + (size_t)a * 2048);
                } else {
                    const float* p = whh + (k - 2048);
                    #pragma unroll
                    for (int a = 0; a < 8; ++a)
                        dst[a] = *reinterpret_cast<const float4*>(p + (size_t)a * 1024);
                }
            };

            ldw(wc, 0);
            const float* xbase = &smem[(bg * 2) * 3072];

            #pragma unroll 2
            for (int i = 0; i < 24; ++i) {
                if (i < 23) ldw(wn, i + 1);
                const int klb = (i * 8 + ksl) * 4;
                #pragma unroll
                for (int q = 0; q < 4; ++q) {
                    const int kl = klb + q;
                    const double2 d0 = *reinterpret_cast<const double2*>(xbase + kl * 4);
                    const double2 d1 = *reinterpret_cast<const double2*>(xbase + 3072 + kl * 4);
                    const unsigned long long xv0 = __double_as_longlong(d0.x);
                    const unsigned long long xv1 = __double_as_longlong(d0.y);
                    const unsigned long long xv2 = __double_as_longlong(d1.x);
                    const unsigned long long xv3 = __double_as_longlong(d1.y);
                    #pragma unroll
                    for (int a = 0; a < 8; ++a) {
                        const float wv = (q == 0) ? wc[a].x : (q == 1) ? wc[a].y
                                       : (q == 2) ? wc[a].z : wc[a].w;
                        unsigned long long w2;
                        asm("mov.b64 %0, {%1, %1};" : "=l"(w2) : "r"(__float_as_uint(wv)));
                        asm("fma.rn.f32x2 %0, %1, %2, %0;" : "+l"(acc[a][0]) : "l"(w2), "l"(xv0));
                        asm("fma.rn.f32x2 %0, %1, %2, %0;" : "+l"(acc[a][1]) : "l"(w2), "l"(xv1));
                        asm("fma.rn.f32x2 %0, %1, %2, %0;" : "+l"(acc[a][2]) : "l"(w2), "l"(xv2));
                        asm("fma.rn.f32x2 %0, %1, %2, %0;" : "+l"(acc[a][3]) : "l"(w2), "l"(xv3));
                    }
                }
                #pragma unroll
                for (int a = 0; a < 8; ++a) wc[a] = wn[a];
            }

            // reduce over the 8 k-slices (lanes at xor offsets 2,4,8; parity
            // bit 0 = batch-group is preserved)
            #pragma unroll
            for (int off = 2; off <= 8; off <<= 1) {
                #pragma unroll
                for (int a = 0; a < 8; ++a)
                    #pragma unroll
                    for (int p = 0; p < 4; ++p) {
                        unsigned lo = (unsigned)acc[a][p];
                        unsigned hi = (unsigned)(acc[a][p] >> 32);
                        lo = __shfl_xor_sync(0xFFFFFFFFu, lo, off);
                        hi = __shfl_xor_sync(0xFFFFFFFFu, hi, off);
                        unsigned long long o = ((unsigned long long)hi << 32) | lo;
                        asm("add.rn.f32x2 %0, %0, %1;" : "+l"(acc[a][p]) : "l"(o));
                    }
            }

            // lane (bg, aw=lane4>>1) writes row j0t+aw, its batch group's 4 pairs
            const int aw = lane4 >> 1;
            #pragma unroll
            for (int a = 0; a < 8; ++a) {
                if (a == aw) {
                    const int j = j0t + a;
                    #pragma unroll
                    for (int p = 0; p < 4; ++p) {
                        const int b0 = bg * 8 + 2 * p;
                        const unsigned long long v = acc[a][p];
                        g_gpart[kb][b0][j]     = __uint_as_float((unsigned)v);
                        g_gpart[kb][b0 + 1][j] = __uint_as_float((unsigned)(v >> 32));
                    }
                }
            }
        }
        grid_barrier();  // B1: gates done

        // ============ LSTM + phi + GMM attention (blocks 0..15) ============
        if (bid < BB) {
            const int b = bid;
            for (int dd = tid; dd < DD; dd += NT) {
                float gi = b_ih[dd]          + b_hh[dd];
                float gf = b_ih[DD + dd]     + b_hh[DD + dd];
                float gg = b_ih[2 * DD + dd] + b_hh[2 * DD + dd];
                float go = b_ih[3 * DD + dd] + b_hh[3 * DD + dd];
                #pragma unroll
                for (int q = 0; q < 4; ++q) {
                    gi += g_gpart[q][b][dd];
                    gf += g_gpart[q][b][DD + dd];
                    gg += g_gpart[q][b][2 * DD + dd];
                    go += g_gpart[q][b][3 * DD + dd];
                }
                const float c = sigf(gf) * g_c[b * DD + dd] + sigf(gi) * tanhf(gg);
                const float h = sigf(go) * tanhf(c);
                g_c[b * DD + dd] = c;
                g_h[b * DD + dd] = h;
            }
            __syncthreads();

            // phi = h @ Wg_w^T + Wg_b  (48 dots of 1024; warp w -> 6 rows)
            {
                const int w = tid >> 5, lane = tid & 31;
                float hreg[32];
                #pragma unroll
                for (int i = 0; i < 32; ++i) hreg[i] = g_h[b * DD + i * 32 + lane];
                for (int mi = 0; mi < 6; ++mi) {
                    const int mm = w * 6 + mi;
                    const float* wr = Wg_w + (size_t)mm * DD;
                    float acc = 0.0f;
                    #pragma unroll
                    for (int i = 0; i < 32; ++i) acc += wr[i * 32 + lane] * hreg[i];
                    #pragma unroll
                    for (int off = 16; off; off >>= 1)
                        acc += __shfl_xor_sync(0xFFFFFFFFu, acc, off);
                    if (lane == 0) sh_phi[mm] = acc + Wg_b[mm];
                }
            }
            __syncthreads();

            if (tid < 32) {
                const int m = tid & 15;
                const float pk = sh_phi[m];
                const float pb = sh_phi[MM + m];
                const float pa = sh_phi[2 * MM + m];
                float mx = pa;
                #pragma unroll
                for (int off = 1; off < 16; off <<= 1)
                    mx = fmaxf(mx, __shfl_xor_sync(0xFFFFFFFFu, mx, off, 16));
                const float e = __expf(pa - mx);
                float sum = e;
                #pragma unroll
                for (int off = 1; off < 16; off <<= 1)
                    sum += __shfl_xor_sync(0xFFFFFFFFu, sum, off, 16);
                if (tid < 16) {
                    sh_alpha[m] = e / sum;
                    sh_ksi[m]   = __expf(pk);
                    sh_binv[m]  = __expf(-pb);
                }
            }
            __syncthreads();

            // attention weights w[b,s] + termination tap
            const int lb = lens[b];
            for (int s = tid; s < SS; s += NT) {
                const float fs = (float)s;
                float aw = 0.0f, ar = 0.0f;
                #pragma unroll
                for (int m = 0; m < MM; ++m) {
                    const float binv = sh_binv[m];
                    const float z  = (fs - sh_ksi[m]) * binv;
                    const float hb = 0.5f * binv;
                    const float fr = sigf(z + hb);
                    const float fl = sigf(z - hb);
                    const float al = sh_alpha[m];
                    aw += al * (fr - fl);
                    ar += al * fr;
                }
                g_watt[b][s] = aw;
                out_align[((size_t)b * TT + t) * SS + s] = aw;
                if (t == TT - 1 && s == lb - 1) out_term[b] = 1.0f - ar;
            }
        }
        grid_barrier();  // B2: h, w ready

        // ===================== ctx = w @ memory ============================
        {
            const int b  = bid >> 3;
            const int d0 = (bid & 7) * 128;
            const int w  = tid >> 5, lane = tid & 31;
            const float* mb = memv + (size_t)b * SS * DD + d0 + lane * 4;
            float4 acc = make_float4(0.f, 0.f, 0.f, 0.f);
            const int sbase = w * 64;
            #pragma unroll 4
            for (int si = 0; si < 64; ++si) {
                const int s = sbase + si;
                const float wv = g_watt[b][s];
                const float4 mv = *reinterpret_cast<const float4*>(mb + (size_t)s * DD);
                acc.x += wv * mv.x; acc.y += wv * mv.y;
                acc.z += wv * mv.z; acc.w += wv * mv.w;
            }
            float4* red = reinterpret_cast<float4*>(smem);
            red[w * 32 + lane] = acc;
            __syncthreads();
            if (tid < 32) {
                float4 r = red[tid];
                #pragma unroll
                for (int q = 1; q < 8; ++q) {
                    const float4 v = red[q * 32 + tid];
                    r.x += v.x; r.y += v.y; r.z += v.z; r.w += v.w;
                }
                const int di = d0 + tid * 4;
                *reinterpret_cast<float4*>(&g_ctx[b * DD + di]) = r;
                if (t == TT - 1)
                    *reinterpret_cast<float4*>(&out_ctx[b * DD + di]) = r;
            }
        }
        grid_barrier();  // B3: ctx ready for next step's gates
    }
}

extern "C" void kernel_launch(void* const* d_in, const int* in_sizes, int n_in,
                              void* d_out, int out_size) {
    (void)in_sizes; (void)n_in; (void)out_size;
    const float* x_in  = (const float*)d_in[0];
    const float* memv  = (const float*)d_in[1];
    const int*   lens  = (const int*)  d_in[2];
    const float* W_ih  = (const float*)d_in[3];
    const float* W_hh  = (const float*)d_in[4];
    const float* b_ih  = (const float*)d_in[5];
    const float* b_hh  = (const float*)d_in[6];
    const float* Wg_w  = (const float*)d_in[7];
    const float* Wg_b  = (const float*)d_in[8];
    tts_kernel<<<NB, NT, 49152>>>(x_in, memv, lens, W_ih, W_hh,
                                  b_ih, b_hh, Wg_w, Wg_b, (float*)d_out);
}

// round 4
// speedup vs baseline: 1.2996x; 1.2437x over previous
#include <cuda_runtime.h>
#include <cstdint>

#define NB 128
#define NT 512
#define BB 16
#define TT 1024
#define DD 1024
#define SS 512
#define MM 16

// ---------------- persistent state (device globals; no allocation) ----------
__device__ float g_h[BB * DD];
__device__ float g_c[BB * DD];
__device__ float g_ctx[BB * DD];
__device__ float g_gpart[4][BB][4 * DD];   // k-split partial gates, 1 MB
__device__ float g_watt[BB][SS];
__device__ unsigned g_count;               // zero-initialized
__device__ volatile unsigned g_gen;

__device__ __forceinline__ float sigf(float x) {
    return __fdividef(1.0f, 1.0f + __expf(-x));
}

// Software grid barrier. Grid = 128 blocks <= 148 SMs => single wave.
__device__ __forceinline__ void grid_barrier() {
    __syncthreads();
    if (threadIdx.x == 0) {
        unsigned gen = g_gen;
        __threadfence();
        unsigned arrived = atomicAdd(&g_count, 1u);
        if (arrived == NB - 1) {
            g_count = 0u;
            __threadfence();
            g_gen = gen + 1u;
        } else {
            while (g_gen == gen) { __nanosleep(32); }
            __threadfence();
        }
    }
    __syncthreads();
}

extern __shared__ float smem[];  // 12288 floats = 48 KB dynamic only

__device__ __forceinline__ uint32_t swz(uint32_t L) {
    return L ^ ((L >> 3) & 0x70u);   // flip 16B-chunk bits 4-6 by bits 7-9
}

__global__ __launch_bounds__(NT, 1) void tts_kernel(
    const float* __restrict__ x_in,    // [B,T,D]
    const float* __restrict__ memv,    // [B,S,D]
    const int*   __restrict__ lens,    // [B]
    const float* __restrict__ W_ih,    // [4096,2048]
    const float* __restrict__ W_hh,    // [4096,1024]
    const float* __restrict__ b_ih,    // [4096]
    const float* __restrict__ b_hh,    // [4096]
    const float* __restrict__ Wg_w,    // [48,1024]
    const float* __restrict__ Wg_b,    // [48]
    float* __restrict__ out)
{
    const int bid = blockIdx.x;
    const int tid = threadIdx.x;

    // phase-disjoint small scratch carved from dynamic smem
    float* sh_phi   = smem;        // 48 floats
    float* sh_ksi   = smem + 48;   // 16
    float* sh_binv  = smem + 64;   // 16
    float* sh_alpha = smem + 80;   // 16

    float* out_ctx   = out;                                  // [B,1,D]
    float* out_align = out + BB * DD;                        // [B,T,S]
    float* out_term  = out + BB * DD + (size_t)BB * TT * SS; // [B,1]

    // ------- init state -------
    for (int i = bid * NT + tid; i < BB * DD; i += NB * NT) {
        g_h[i] = 0.0f; g_c[i] = 0.0f; g_ctx[i] = 0.0f;
    }
    grid_barrier();

    // gates GEMM mapping: 32 j-tiles x 4 k-splits
    const int jt = bid >> 2;            // 0..31 -> 128 j's each
    const int kb = bid & 3;             // 0..3  -> 768 k's each
    const int kbase = kb * 768;

    // within block: 32 j-groups (4 rows) x [2 batch-groups x 8 k-slices]
    const int jg    = tid >> 4;         // 0..31
    const int lane4 = tid & 15;
    const int bg    = lane4 & 1;        // batches bg*8 .. bg*8+7
    const int ksl   = lane4 >> 1;       // 0..7 k-slice (24 quads each)
    const int j0t   = jt * 128 + jg * 4;

    const float* wih = W_ih + (size_t)j0t * 2048;
    const float* whh = W_hh + (size_t)j0t * 1024;

    for (int t = 0; t < TT; ++t) {
        // ===================== stage x slice into smem (swizzled) ==========
        #pragma unroll 4
        for (int b = 0; b < BB; ++b) {
            const int cb = b >> 2, bl = b & 3;
            {
                const int kl = tid;              // < 768
                const int k = kbase + kl;
                float v;
                if (k < DD)            v = x_in[((size_t)b * TT + t) * DD + k];
                else if (k < 2 * DD)   v = g_ctx[b * DD + (k - DD)];
                else                   v = g_h[b * DD + (k - 2 * DD)];
                const uint32_t L = swz((uint32_t)(kl * 16 + bl * 4));
                *reinterpret_cast<float*>(
                    reinterpret_cast<char*>(smem) + cb * 12288 + L) = v;
            }
            if (tid < 256) {
                const int kl = tid + 512;
                const int k = kbase + kl;
                float v;
                if (k < DD)            v = x_in[((size_t)b * TT + t) * DD + k];
                else if (k < 2 * DD)   v = g_ctx[b * DD + (k - DD)];
                else                   v = g_h[b * DD + (k - 2 * DD)];
                const uint32_t L = swz((uint32_t)(kl * 16 + bl * 4));
                *reinterpret_cast<float*>(
                    reinterpret_cast<char*>(smem) + cb * 12288 + L) = v;
            }
        }
        __syncthreads();

        // ======= gates GEMM: float4 weights, prefetch, packed f32x2 =======
        {
            unsigned long long acc[4][4];
            #pragma unroll
            for (int a = 0; a < 4; ++a)
                #pragma unroll
                for (int p = 0; p < 4; ++p) acc[a][p] = 0ull;

            float4 wc[4], wn[4];

            auto ldw = [&](float4* dst, int i) {
                const int off = (i * 8 + ksl) * 4;   // 0..767
                const int k = kbase + off;
                if (k < 2048) {
                    const float* p = wih + k;
                    #pragma unroll
                    for (int a = 0; a < 4; ++a)
                        dst[a] = *reinterpret_cast<const float4*>(p + (size_t)a * 2048);
                } else {
                    const float* p = whh + (k - 2048);
                    #pragma unroll
                    for (int a = 0; a < 4; ++a)
                        dst[a] = *reinterpret_cast<const float4*>(p + (size_t)a * 1024);
                }
            };

            ldw(wc, 0);
            const char* xb = reinterpret_cast<const char*>(smem) + (bg * 2) * 12288;

            #pragma unroll 2
            for (int i = 0; i < 24; ++i) {
                if (i < 23) ldw(wn, i + 1);
                const int klb = (i * 8 + ksl) * 4;
                #pragma unroll
                for (int q = 0; q < 4; ++q) {
                    const uint32_t L = swz((uint32_t)((klb + q) * 16));
                    const double2 d0 = *reinterpret_cast<const double2*>(xb + L);
                    const double2 d1 = *reinterpret_cast<const double2*>(xb + 12288 + L);
                    const unsigned long long xv0 = __double_as_longlong(d0.x);
                    const unsigned long long xv1 = __double_as_longlong(d0.y);
                    const unsigned long long xv2 = __double_as_longlong(d1.x);
                    const unsigned long long xv3 = __double_as_longlong(d1.y);
                    #pragma unroll
                    for (int a = 0; a < 4; ++a) {
                        const float wv = (q == 0) ? wc[a].x : (q == 1) ? wc[a].y
                                       : (q == 2) ? wc[a].z : wc[a].w;
                        unsigned long long w2;
                        asm("mov.b64 %0, {%1, %1};" : "=l"(w2) : "r"(__float_as_uint(wv)));
                        asm("fma.rn.f32x2 %0, %1, %2, %0;" : "+l"(acc[a][0]) : "l"(w2), "l"(xv0));
                        asm("fma.rn.f32x2 %0, %1, %2, %0;" : "+l"(acc[a][1]) : "l"(w2), "l"(xv1));
                        asm("fma.rn.f32x2 %0, %1, %2, %0;" : "+l"(acc[a][2]) : "l"(w2), "l"(xv2));
                        asm("fma.rn.f32x2 %0, %1, %2, %0;" : "+l"(acc[a][3]) : "l"(w2), "l"(xv3));
                    }
                }
                #pragma unroll
                for (int a = 0; a < 4; ++a) wc[a] = wn[a];
            }

            // reduce over the 8 k-slices (xor offsets 2,4,8; bg bit preserved)
            #pragma unroll
            for (int off = 2; off <= 8; off <<= 1) {
                #pragma unroll
                for (int a = 0; a < 4; ++a)
                    #pragma unroll
                    for (int p = 0; p < 4; ++p) {
                        unsigned lo = (unsigned)acc[a][p];
                        unsigned hi = (unsigned)(acc[a][p] >> 32);
                        lo = __shfl_xor_sync(0xFFFFFFFFu, lo, off);
                        hi = __shfl_xor_sync(0xFFFFFFFFu, hi, off);
                        unsigned long long o = ((unsigned long long)hi << 32) | lo;
                        asm("add.rn.f32x2 %0, %0, %1;" : "+l"(acc[a][p]) : "l"(o));
                    }
            }

            // lane (bg,ksl): row a = ksl>>1, pairs p with p>>1 == (ksl&1)
            const int arow = ksl >> 1;
            const int psel = ksl & 1;
            #pragma unroll
            for (int a = 0; a < 4; ++a) {
                #pragma unroll
                for (int p = 0; p < 4; ++p) {
                    if (a == arow && (p >> 1) == psel) {
                        const int j = j0t + a;
                        const int b0 = bg * 8 + 2 * p;
                        const unsigned long long v = acc[a][p];
                        g_gpart[kb][b0][j]     = __uint_as_float((unsigned)v);
                        g_gpart[kb][b0 + 1][j] = __uint_as_float((unsigned)(v >> 32));
                    }
                }
            }
        }
        grid_barrier();  // B1: gates done

        // ============ LSTM + phi + GMM attention (blocks 0..15) ============
        if (bid < BB) {
            const int b = bid;
            #pragma unroll
            for (int r = 0; r < 2; ++r) {
                const int dd = r * NT + tid;
                float gi = b_ih[dd]          + b_hh[dd];
                float gf = b_ih[DD + dd]     + b_hh[DD + dd];
                float gg = b_ih[2 * DD + dd] + b_hh[2 * DD + dd];
                float go = b_ih[3 * DD + dd] + b_hh[3 * DD + dd];
                #pragma unroll
                for (int q = 0; q < 4; ++q) {
                    gi += g_gpart[q][b][dd];
                    gf += g_gpart[q][b][DD + dd];
                    gg += g_gpart[q][b][2 * DD + dd];
                    go += g_gpart[q][b][3 * DD + dd];
                }
                const float c = sigf(gf) * g_c[b * DD + dd] + sigf(gi) * tanhf(gg);
                const float h = sigf(go) * tanhf(c);
                g_c[b * DD + dd] = c;
                g_h[b * DD + dd] = h;
            }
            __syncthreads();

            // phi = h @ Wg_w^T + Wg_b  (48 dots of 1024; warp w -> 3 rows)
            {
                const int w = tid >> 5, lane = tid & 31;
                float hreg[32];
                #pragma unroll
                for (int i = 0; i < 32; ++i) hreg[i] = g_h[b * DD + i * 32 + lane];
                #pragma unroll
                for (int mi = 0; mi < 3; ++mi) {
                    const int mm = w * 3 + mi;
                    const float* wr = Wg_w + (size_t)mm * DD;
                    float acc = 0.0f;
                    #pragma unroll
                    for (int i = 0; i < 32; ++i) acc += wr[i * 32 + lane] * hreg[i];
                    #pragma unroll
                    for (int off = 16; off; off >>= 1)
                        acc += __shfl_xor_sync(0xFFFFFFFFu, acc, off);
                    if (lane == 0) sh_phi[mm] = acc + Wg_b[mm];
                }
            }
            __syncthreads();

            if (tid < 32) {
                const int m = tid & 15;
                const float pk = sh_phi[m];
                const float pb = sh_phi[MM + m];
                const float pa = sh_phi[2 * MM + m];
                float mx = pa;
                #pragma unroll
                for (int off = 1; off < 16; off <<= 1)
                    mx = fmaxf(mx, __shfl_xor_sync(0xFFFFFFFFu, mx, off, 16));
                const float e = __expf(pa - mx);
                float sum = e;
                #pragma unroll
                for (int off = 1; off < 16; off <<= 1)
                    sum += __shfl_xor_sync(0xFFFFFFFFu, sum, off, 16);
                if (tid < 16) {
                    sh_alpha[m] = e / sum;
                    sh_ksi[m]   = __expf(pk);
                    sh_binv[m]  = __expf(-pb);
                }
            }
            __syncthreads();

            // attention weights w[b,s] + termination tap (one s per thread)
            {
                const int s = tid;  // NT == SS
                const int lb = lens[b];
                const float fs = (float)s;
                float aw = 0.0f, ar = 0.0f;
                #pragma unroll
                for (int m = 0; m < MM; ++m) {
                    const float binv = sh_binv[m];
                    const float z  = (fs - sh_ksi[m]) * binv;
                    const float hb = 0.5f * binv;
                    const float fr = sigf(z + hb);
                    const float fl = sigf(z - hb);
                    const float al = sh_alpha[m];
                    aw += al * (fr - fl);
                    ar += al * fr;
                }
                g_watt[b][s] = aw;
                out_align[((size_t)b * TT + t) * SS + s] = aw;
                if (t == TT - 1 && s == lb - 1) out_term[b] = 1.0f - ar;
            }
        }
        grid_barrier();  // B2: h, w ready

        // ===================== ctx = w @ memory ============================
        {
            const int b  = bid >> 3;
            const int d0 = (bid & 7) * 128;
            const int w  = tid >> 5, lane = tid & 31;
            const float* mb = memv + (size_t)b * SS * DD + d0 + lane * 4;
            float4 acc = make_float4(0.f, 0.f, 0.f, 0.f);
            const int sbase = w * 32;
            #pragma unroll 4
            for (int si = 0; si < 32; ++si) {
                const int s = sbase + si;
                const float wv = g_watt[b][s];
                const float4 mv = *reinterpret_cast<const float4*>(mb + (size_t)s * DD);
                acc.x += wv * mv.x; acc.y += wv * mv.y;
                acc.z += wv * mv.z; acc.w += wv * mv.w;
            }
            float4* red = reinterpret_cast<float4*>(smem);
            red[w * 32 + lane] = acc;
            __syncthreads();
            if (tid < 32) {
                float4 r = red[tid];
                #pragma unroll
                for (int q = 1; q < 16; ++q) {
                    const float4 v = red[q * 32 + tid];
                    r.x += v.x; r.y += v.y; r.z += v.z; r.w += v.w;
                }
                const int di = d0 + tid * 4;
                *reinterpret_cast<float4*>(&g_ctx[b * DD + di]) = r;
                if (t == TT - 1)
                    *reinterpret_cast<float4*>(&out_ctx[b * DD + di]) = r;
            }
        }
        grid_barrier();  // B3: ctx ready for next step's gates
    }
}

extern "C" void kernel_launch(void* const* d_in, const int* in_sizes, int n_in,
                              void* d_out, int out_size) {
    (void)in_sizes; (void)n_in; (void)out_size;
    const float* x_in  = (const float*)d_in[0];
    const float* memv  = (const float*)d_in[1];
    const int*   lens  = (const int*)  d_in[2];
    const float* W_ih  = (const float*)d_in[3];
    const float* W_hh  = (const float*)d_in[4];
    const float* b_ih  = (const float*)d_in[5];
    const float* b_hh  = (const float*)d_in[6];
    const float* Wg_w  = (const float*)d_in[7];
    const float* Wg_b  = (const float*)d_in[8];
    tts_kernel<<<NB, NT, 49152>>>(x_in, memv, lens, W_ih, W_hh,
                                  b_ih, b_hh, Wg_w, Wg_b, (float*)d_out);
}